// round 16
// baseline (speedup 1.0000x reference)
#include <cuda_runtime.h>
#include <cuda_fp16.h>
#include <math.h>
#include <stdint.h>

#define N_PTS   1000000
#define NSEG    64
#define AFFD    16
#define AH      64
#define AL      32
#define AA      8

#define TPB     128
#define WARPS   4
#define TPW     4                                   // tiles per warp
#define TILES_PER_CTA (WARPS * TPW)                 // 16
#define NUM_WT  (N_PTS / 32)                        // 31250 warp-tiles (exact)
#define NCTA    ((NUM_WT + TILES_PER_CTA - 1) / TILES_PER_CTA)  // 1954

#define ACC_STRIDE 18   // 16 aff sums, err sum, count
#define FULL 0xffffffffu

// global scratch (no allocs allowed)
__device__ float g_accum[NSEG * ACC_STRIDE];
__device__ float g_gh[NSEG * 3 * AH];   // precomputed agent_h @ Wh + bh

// ---- fp16 helpers ----
__device__ __forceinline__ uint32_t pack_h2(float lo, float hi) {
    __half2 h = __floats2half2_rn(lo, hi);
    return *reinterpret_cast<uint32_t*>(&h);
}
// split (x,y) into fp16 hi pair and 64x-scaled fp16 residual pair
__device__ __forceinline__ void split_f16(float x, float y, uint32_t& hi, uint32_t& lo) {
    __half2 h = __floats2half2_rn(x, y);
    float2 b = __half22float2(h);
    __half2 l = __floats2half2_rn((x - b.x) * 64.0f, (y - b.y) * 64.0f);
    hi = *reinterpret_cast<uint32_t*>(&h);
    lo = *reinterpret_cast<uint32_t*>(&l);
}
__device__ __forceinline__ void mma_f16(float (&c)[4], const uint32_t (&a)[4], uint2 b) {
    asm volatile(
        "mma.sync.aligned.m16n8k16.row.col.f32.f16.f16.f32 "
        "{%0,%1,%2,%3}, {%4,%5,%6,%7}, {%8,%9}, {%0,%1,%2,%3};"
        : "+f"(c[0]), "+f"(c[1]), "+f"(c[2]), "+f"(c[3])
        : "r"(a[0]), "r"(a[1]), "r"(a[2]), "r"(a[3]), "r"(b.x), "r"(b.y));
}

// ---- tf32 helpers (layer1, K=4 real, k8 tile with hi|lo folded) ----
__device__ __forceinline__ uint32_t cvt_tf32(float f) {
    uint32_t r;
    asm("cvt.rna.tf32.f32 %0, %1;" : "=r"(r) : "f"(f));
    return r;
}
// A cols 0-3 = hi, cols 4-7 = lo; B rows 4-7 duplicate rows 0-3 (b1 == b0).
__device__ __forceinline__ void mma_tf32k8(float (&c)[4],
                                           uint32_t a0, uint32_t a1,
                                           uint32_t a2, uint32_t a3,
                                           uint32_t b0) {
    asm volatile(
        "mma.sync.aligned.m16n8k8.row.col.f32.tf32.tf32.f32 "
        "{%0,%1,%2,%3}, {%4,%5,%6,%7}, {%8,%8}, {%0,%1,%2,%3};"
        : "+f"(c[0]), "+f"(c[1]), "+f"(c[2]), "+f"(c[3])
        : "r"(a0), "r"(a1), "r"(a2), "r"(a3), "r"(b0));
}

__global__ __launch_bounds__(TPB, 6) void point_kernel(
    const float* __restrict__ pos, const int* __restrict__ batch,
    const float* __restrict__ Wf1, const float* __restrict__ bf1,
    const float* __restrict__ Wf2, const float* __restrict__ bf2,
    const float* __restrict__ Wg1, const float* __restrict__ bg1,
    const float* __restrict__ Wg2, const float* __restrict__ bg2,
    const float* __restrict__ agent_h, const float* __restrict__ Wh,
    const float* __restrict__ bh,
    float* __restrict__ out_aff, float* __restrict__ out_recon,
    float* __restrict__ out_cspatial)
{
    __shared__ uint32_t sB1[512];                        // [nt(16)][lane] tf32
    __shared__ uint2    sB2h[512], sB2s[512];            // [kt(8)][ni(2)][lane]
    __shared__ uint2    sB3h[512];                       // [nt(16)][lane] hi-only
    __shared__ uint2    sB4h[256];                       // [kt4(8)][lane] (Wg2, N=8 pad, hi-only)
    __shared__ float sbg1[128];
    __shared__ float sbf2[16];
    __shared__ float sacc[NSEG * ACC_STRIDE];
    __shared__ float s_h0[AH];

    const int tid = threadIdx.x;
    const int lane = tid & 31, wid = tid >> 5;
    const int gid = lane >> 2, tig = lane & 3;

    // ---- CTAs 0..63: precompute gh = agent_h @ Wh + bh (input-only; overlaps) ----
    if (blockIdx.x < NSEG) {
        int b = blockIdx.x;
        if (tid < AH) s_h0[tid] = agent_h[b * AH + tid];
        __syncthreads();
        for (int o = tid; o < 3 * AH; o += TPB) {
            float acc = bh[o];
            #pragma unroll 8
            for (int k = 0; k < AH; k++)
                acc = fmaf(s_h0[k], Wh[k * 3 * AH + o], acc);
            g_gh[b * 3 * AH + o] = acc;
        }
    }

    // ---- CTA init: pack B fragments from gmem weights (L1/L2 resident) ----
    for (int s = tid; s < 512; s += TPB) {
        int ls = s & 31, gs = ls >> 2, ts = ls & 3;
        {   // B1 (tf32): rows 0..2 = Wf1, 3 = bf1
            int nt = s >> 5;
            int n = nt * 8 + gs;
            float v = (ts == 0) ? Wf1[n] : (ts == 1) ? Wf1[128 + n]
                    : (ts == 2) ? Wf1[256 + n] : bf1[n];
            sB1[s] = cvt_tf32(v);
        }
        {   // B2: Wf2 [128k x 16n], slot s = (kt*2+ni)*32 + lane
            int ni = (s >> 5) & 1, kt = s >> 6;
            int n = ni * 8 + gs;
            int k0 = kt * 16 + 2 * ts;
            float w00 = Wf2[k0 * 16 + n],       w01 = Wf2[(k0 + 1) * 16 + n];
            float w10 = Wf2[(k0 + 8) * 16 + n], w11 = Wf2[(k0 + 9) * 16 + n];
            sB2h[s] = make_uint2(pack_h2(w00, w01), pack_h2(w10, w11));
            float q00 = __half2float(__float2half_rn(w00)) * 0.015625f;
            float q01 = __half2float(__float2half_rn(w01)) * 0.015625f;
            float q10 = __half2float(__float2half_rn(w10)) * 0.015625f;
            float q11 = __half2float(__float2half_rn(w11)) * 0.015625f;
            sB2s[s] = make_uint2(pack_h2(q00, q01), pack_h2(q10, q11));
        }
        {   // B3: Wg1 [16k x 128n], hi-only, slot s = nt*32 + lane
            int nt = s >> 5;
            int n = nt * 8 + gs;
            int k0 = 2 * ts;
            float v00 = Wg1[k0 * 128 + n],       v01 = Wg1[(k0 + 1) * 128 + n];
            float v10 = Wg1[(k0 + 8) * 128 + n], v11 = Wg1[(k0 + 9) * 128 + n];
            sB3h[s] = make_uint2(pack_h2(v00, v01), pack_h2(v10, v11));
        }
    }
    // B4: Wg2 [128k x 3n] padded to N=8, hi-only (recon tolerates fp16 rounding)
    for (int s = tid; s < 256; s += TPB) {
        int ls = s & 31, gs = ls >> 2, ts = ls & 3;
        int kt4 = s >> 5;
        int k0 = kt4 * 16 + 2 * ts;
        float v0 = (gs < 3) ? Wg2[k0 * 3 + gs] : 0.f;
        float v1 = (gs < 3) ? Wg2[(k0 + 1) * 3 + gs] : 0.f;
        float v2 = (gs < 3) ? Wg2[(k0 + 8) * 3 + gs] : 0.f;
        float v3 = (gs < 3) ? Wg2[(k0 + 9) * 3 + gs] : 0.f;
        sB4h[s] = make_uint2(pack_h2(v0, v1), pack_h2(v2, v3));
    }
    if (tid < 128) {
        sbg1[tid] = bg1[tid];
        if (tid < 16) sbf2[tid] = bf2[tid];
    }
    for (int i = tid; i < NSEG * ACC_STRIDE; i += TPB) sacc[i] = 0.f;
    __syncthreads();

    // ---- main: 4 warp-tiles per warp, sequential (init amortized) ----
    for (int t = 0; t < TPW; t++) {
        const int wt = blockIdx.x * TILES_PER_CTA + wid * TPW + t;
        if (wt >= NUM_WT) break;

        const int base = wt * 32;
        const int p = base + lane;
        const float px = pos[p * 3], py = pos[p * 3 + 1], pz = pos[p * 3 + 2];
        const int sg = batch[p];

        // ---- layer1 A fragments via direct LDG (row = base+gid+8j, col = tig) ----
        uint32_t A1hi[2][2], A1lo[2][2];
        #pragma unroll
        for (int j = 0; j < 4; j++) {
            int row = base + gid + 8 * j;
            int idx = min(row * 3 + tig, 3 * N_PTS - 1);
            float vm = pos[idx];
            float v = (tig == 3) ? 1.0f : vm;
            uint32_t hi = cvt_tf32(v);
            A1hi[j >> 1][j & 1] = hi;
            A1lo[j >> 1][j & 1] = cvt_tf32(v - __uint_as_float(hi));
        }

        // ---- layer2 accumulators (aff), init with bf2 bias ----
        float C2[2][2][4];
        #pragma unroll
        for (int ni = 0; ni < 2; ni++) {
            float be = sbf2[ni * 8 + 2 * tig];
            float bo = sbf2[ni * 8 + 2 * tig + 1];
            #pragma unroll
            for (int mi = 0; mi < 2; mi++) {
                C2[mi][ni][0] = be; C2[mi][ni][1] = bo;
                C2[mi][ni][2] = be; C2[mi][ni][3] = bo;
            }
        }

        // ---- fused layer1(tf32 k8) -> relu/split -> layer2(fp16 2-term) ----
        #pragma unroll 2
        for (int kt = 0; kt < 8; kt++) {
            float C1[2][2][4];
            uint32_t b_a = sB1[(2 * kt) * 32 + lane];
            uint32_t b_b = sB1[(2 * kt + 1) * 32 + lane];
            #pragma unroll
            for (int ntl = 0; ntl < 2; ntl++)
                #pragma unroll
                for (int mi = 0; mi < 2; mi++) {
                    float (&c)[4] = C1[ntl][mi];
                    c[0] = 0.f; c[1] = 0.f; c[2] = 0.f; c[3] = 0.f;
                    mma_tf32k8(c, A1hi[mi][0], A1hi[mi][1],
                                  A1lo[mi][0], A1lo[mi][1],
                                  ntl ? b_b : b_a);
                }

            uint32_t a2h[2][4], a2l[2][4];
            #pragma unroll
            for (int mi = 0; mi < 2; mi++) {
                float r00 = fmaxf(C1[0][mi][0], 0.f), r01 = fmaxf(C1[0][mi][1], 0.f);
                float r02 = fmaxf(C1[0][mi][2], 0.f), r03 = fmaxf(C1[0][mi][3], 0.f);
                float r10 = fmaxf(C1[1][mi][0], 0.f), r11 = fmaxf(C1[1][mi][1], 0.f);
                float r12 = fmaxf(C1[1][mi][2], 0.f), r13 = fmaxf(C1[1][mi][3], 0.f);
                split_f16(r00, r01, a2h[mi][0], a2l[mi][0]);
                split_f16(r02, r03, a2h[mi][1], a2l[mi][1]);
                split_f16(r10, r11, a2h[mi][2], a2l[mi][2]);
                split_f16(r12, r13, a2h[mi][3], a2l[mi][3]);
            }

            #pragma unroll
            for (int ni = 0; ni < 2; ni++) {
                uint2 bhv = sB2h[(kt * 2 + ni) * 32 + lane];
                uint2 bsv = sB2s[(kt * 2 + ni) * 32 + lane];
                #pragma unroll
                for (int mi = 0; mi < 2; mi++) {
                    mma_f16(C2[mi][ni], a2h[mi], bhv);
                    mma_f16(C2[mi][ni], a2l[mi], bsv);
                }
            }
        }

        // ---- store affordances: direct STG.64 ----
        #pragma unroll
        for (int mi = 0; mi < 2; mi++)
            #pragma unroll
            for (int ni = 0; ni < 2; ni++) {
                int r0 = base + 16 * mi + gid;
                int c0 = ni * 8 + 2 * tig;
                *(float2*)(out_aff + (size_t)r0 * 16 + c0) =
                    make_float2(C2[mi][ni][0], C2[mi][ni][1]);
                *(float2*)(out_aff + (size_t)(r0 + 8) * 16 + c0) =
                    make_float2(C2[mi][ni][2], C2[mi][ni][3]);
            }

        // ---- layer3 A fragments directly from C2 (hi-only) ----
        uint32_t a3h[2][4];
        #pragma unroll
        for (int mi = 0; mi < 2; mi++) {
            a3h[mi][0] = pack_h2(C2[mi][0][0], C2[mi][0][1]);
            a3h[mi][1] = pack_h2(C2[mi][0][2], C2[mi][0][3]);
            a3h[mi][2] = pack_h2(C2[mi][1][0], C2[mi][1][1]);
            a3h[mi][3] = pack_h2(C2[mi][1][2], C2[mi][1][3]);
        }

        // ---- layer3 (fp16 hi-only MMA) -> relu/pack -> layer4 (fp16 hi-only MMA) ----
        float C4[2][4];
        C4[0][0] = 0.f; C4[0][1] = 0.f; C4[0][2] = 0.f; C4[0][3] = 0.f;
        C4[1][0] = 0.f; C4[1][1] = 0.f; C4[1][2] = 0.f; C4[1][3] = 0.f;

        #pragma unroll 2
        for (int kt4 = 0; kt4 < 8; kt4++) {
            int nt0 = 2 * kt4, nt1 = 2 * kt4 + 1;
            uint2 bh0 = sB3h[nt0 * 32 + lane];
            uint2 bh1 = sB3h[nt1 * 32 + lane];
            float be0 = sbg1[nt0 * 8 + 2 * tig], bo0 = sbg1[nt0 * 8 + 2 * tig + 1];
            float be1 = sbg1[nt1 * 8 + 2 * tig], bo1 = sbg1[nt1 * 8 + 2 * tig + 1];
            uint2 b4h = sB4h[kt4 * 32 + lane];
            #pragma unroll
            for (int mi = 0; mi < 2; mi++) {
                float gE[4] = {be0, bo0, be0, bo0};
                mma_f16(gE, a3h[mi], bh0);
                float gO[4] = {be1, bo1, be1, bo1};
                mma_f16(gO, a3h[mi], bh1);
                uint32_t a4h[4];
                a4h[0] = pack_h2(fmaxf(gE[0], 0.f), fmaxf(gE[1], 0.f));
                a4h[1] = pack_h2(fmaxf(gE[2], 0.f), fmaxf(gE[3], 0.f));
                a4h[2] = pack_h2(fmaxf(gO[0], 0.f), fmaxf(gO[1], 0.f));
                a4h[3] = pack_h2(fmaxf(gO[2], 0.f), fmaxf(gO[3], 0.f));
                mma_f16(C4[mi], a4h, b4h);
            }
        }

        // ---- extract recon for this lane's own row (row = lane) ----
        const int src0 = (lane & 7) * 4;
        const int src1 = src0 + 1;
        const bool h8 = (lane & 8) != 0;
        const bool h16 = (lane & 16) != 0;
        float xa = __shfl_sync(FULL, C4[0][0], src0);
        float xb = __shfl_sync(FULL, C4[0][2], src0);
        float xc = __shfl_sync(FULL, C4[1][0], src0);
        float xd = __shfl_sync(FULL, C4[1][2], src0);
        float ya = __shfl_sync(FULL, C4[0][1], src0);
        float yb = __shfl_sync(FULL, C4[0][3], src0);
        float yc = __shfl_sync(FULL, C4[1][1], src0);
        float yd = __shfl_sync(FULL, C4[1][3], src0);
        float za = __shfl_sync(FULL, C4[0][0], src1);
        float zb = __shfl_sync(FULL, C4[0][2], src1);
        float zc = __shfl_sync(FULL, C4[1][0], src1);
        float zd = __shfl_sync(FULL, C4[1][2], src1);
        float rxx = (h16 ? (h8 ? xd : xc) : (h8 ? xb : xa)) + bg2[0];
        float ryy = (h16 ? (h8 ? yd : yc) : (h8 ? yb : ya)) + bg2[1];
        float rzz = (h16 ? (h8 ? zd : zc) : (h8 ? zb : za)) + bg2[2];

        float dx = px - rxx, dy = py - ryy, dz = pz - rzz;
        float e = fmaf(dx, dx, fmaf(dy, dy, dz * dz));
        out_recon[(size_t)p * 3 + 0] = rxx;
        out_recon[(size_t)p * 3 + 1] = ryy;
        out_recon[(size_t)p * 3 + 2] = rzz;
        out_cspatial[p] = e;

        // ---- segment reduction ----
        int sg0 = __shfl_sync(FULL, sg, 0);
        bool uni = __all_sync(FULL, sg == sg0);
        if (uni) {
            float s0 = C2[0][0][0] + C2[0][0][2] + C2[1][0][0] + C2[1][0][2];
            float s1 = C2[0][0][1] + C2[0][0][3] + C2[1][0][1] + C2[1][0][3];
            float s2 = C2[0][1][0] + C2[0][1][2] + C2[1][1][0] + C2[1][1][2];
            float s3 = C2[0][1][1] + C2[0][1][3] + C2[1][1][1] + C2[1][1][3];
            #pragma unroll
            for (int off = 4; off <= 16; off <<= 1) {
                s0 += __shfl_xor_sync(FULL, s0, off);
                s1 += __shfl_xor_sync(FULL, s1, off);
                s2 += __shfl_xor_sync(FULL, s2, off);
                s3 += __shfl_xor_sync(FULL, s3, off);
            }
            if (lane < 4) {
                float* a = sacc + sg0 * ACC_STRIDE;
                atomicAdd(a + 2 * tig, s0);
                atomicAdd(a + 2 * tig + 1, s1);
                atomicAdd(a + 2 * tig + 8, s2);
                atomicAdd(a + 2 * tig + 9, s3);
            }
            float es = e;
            #pragma unroll
            for (int off = 1; off <= 16; off <<= 1)
                es += __shfl_xor_sync(FULL, es, off);
            if (lane == 0) {
                atomicAdd(sacc + sg0 * ACC_STRIDE + 16, es);
                atomicAdd(sacc + sg0 * ACC_STRIDE + 17, 32.f);
            }
        } else {
            int bseg[4];
            #pragma unroll
            for (int j = 0; j < 4; j++) bseg[j] = batch[base + gid + 8 * j];
            #pragma unroll
            for (int mi = 0; mi < 2; mi++) {
                float* a0 = sacc + bseg[2 * mi] * ACC_STRIDE;
                float* a1 = sacc + bseg[2 * mi + 1] * ACC_STRIDE;
                #pragma unroll
                for (int ni = 0; ni < 2; ni++) {
                    atomicAdd(a0 + ni * 8 + 2 * tig,     C2[mi][ni][0]);
                    atomicAdd(a0 + ni * 8 + 2 * tig + 1, C2[mi][ni][1]);
                    atomicAdd(a1 + ni * 8 + 2 * tig,     C2[mi][ni][2]);
                    atomicAdd(a1 + ni * 8 + 2 * tig + 1, C2[mi][ni][3]);
                }
            }
            atomicAdd(sacc + sg * ACC_STRIDE + 16, e);
            atomicAdd(sacc + sg * ACC_STRIDE + 17, 1.f);
        }
    }
    __syncthreads();

    // ---- flush CTA's segment range (batch sorted; 512 points per CTA) ----
    int first = blockIdx.x * TILES_PER_CTA * 32;
    if (first < N_PTS) {
        int last = min(first + TILES_PER_CTA * 32 - 1, N_PTS - 1);
        int smin = batch[first];
        int smax = batch[last];
        int total = (smax - smin + 1) * ACC_STRIDE;
        for (int t = tid; t < total; t += TPB) {
            float v = sacc[smin * ACC_STRIDE + t];
            if (v != 0.f) atomicAdd(&g_accum[smin * ACC_STRIDE + t], v);
        }
    }
}

// fast transcendentals (2-ulp __expf): error ~1e-6, negligible vs 1e-3 budget
__device__ __forceinline__ float fast_sigmoid(float x) {
    return 1.0f / (1.0f + __expf(-x));
}
__device__ __forceinline__ float fast_tanh(float x) {
    return 2.0f / (1.0f + __expf(-2.0f * x)) - 1.0f;
}

// one thread per GRU gate output; gh side precomputed by point_kernel
__global__ __launch_bounds__(192) void agent_kernel(
    const float* __restrict__ agent_h,
    const float* __restrict__ Wx, const float* __restrict__ bx,
    const float* __restrict__ Wlat, const float* __restrict__ blat,
    const float* __restrict__ Wact, const float* __restrict__ bact,
    float* __restrict__ out_csig, float* __restrict__ out_action,
    float* __restrict__ out_hnext)
{
    int b = blockIdx.x;
    int u = threadIdx.x;   // 0..191
    __shared__ float s_aff[AFFD];
    __shared__ float s_h[AH];
    __shared__ float sRZ[2 * AH];
    __shared__ float sGN[AH];
    __shared__ float sHN[AH];
    __shared__ float s_hn[AH];
    __shared__ float s_lat[AL];

    float cnt = g_accum[b * ACC_STRIDE + 17];
    float denom = fmaxf(cnt, 1.0f);
    if (u < AFFD) s_aff[u] = g_accum[b * ACC_STRIDE + u] / denom;
    if (u == 0)   out_csig[b] = g_accum[b * ACC_STRIDE + 16] / denom;
    if (u < AH)   s_h[u] = agent_h[b * AH + u];
    __syncthreads();

    // re-zero accumulator for next graph replay (after all reads)
    if (u < ACC_STRIDE) g_accum[b * ACC_STRIDE + u] = 0.0f;

    float gx = bx[u];
    #pragma unroll
    for (int k = 0; k < AFFD; k++)
        gx = fmaf(s_aff[k], Wx[k * 192 + u], gx);
    float gh = g_gh[b * 192 + u];   // precomputed in point_kernel

    if (u < 2 * AH) sRZ[u] = gx + gh;
    else { sGN[u - 2 * AH] = gx; sHN[u - 2 * AH] = gh; }
    __syncthreads();

    if (u < AH) {
        float r = fast_sigmoid(sRZ[u]);
        float z = fast_sigmoid(sRZ[AH + u]);
        float n = fast_tanh(sGN[u] + r * sHN[u]);
        float hn = (1.0f - z) * n + z * s_h[u];
        out_hnext[b * AH + u] = hn;
        s_hn[u] = hn;
    }
    __syncthreads();

    if (u < AL) {
        float acc = blat[u];
        #pragma unroll 8
        for (int k = 0; k < AH; k++) acc = fmaf(s_hn[k], Wlat[k * AL + u], acc);
        s_lat[u] = fast_tanh(acc);
    }
    __syncthreads();

    if (u < AA) {
        float acc = bact[u];
        #pragma unroll
        for (int k = 0; k < AL; k++) acc = fmaf(s_lat[k], Wact[k * AA + u], acc);
        out_action[b * AA + u] = acc;
    }
}

extern "C" void kernel_launch(void* const* d_in, const int* in_sizes, int n_in,
                              void* d_out, int out_size) {
    const float* pos   = (const float*)d_in[0];
    const int*   batch = (const int*)d_in[1];
    const float* agent_h = (const float*)d_in[2];
    const float* Wf1 = (const float*)d_in[5];
    const float* bf1 = (const float*)d_in[6];
    const float* Wf2 = (const float*)d_in[7];
    const float* bf2 = (const float*)d_in[8];
    const float* Wg1 = (const float*)d_in[9];
    const float* bg1 = (const float*)d_in[10];
    const float* Wg2 = (const float*)d_in[11];
    const float* bg2 = (const float*)d_in[12];
    const float* Wx  = (const float*)d_in[13];
    const float* Wh  = (const float*)d_in[14];
    const float* bx  = (const float*)d_in[15];
    const float* bh  = (const float*)d_in[16];
    const float* Wlat = (const float*)d_in[17];
    const float* blat = (const float*)d_in[18];
    const float* Wact = (const float*)d_in[19];
    const float* bact = (const float*)d_in[20];

    float* out = (float*)d_out;
    float* out_aff      = out;                                        // N*16
    float* out_recon    = out + (size_t)N_PTS * AFFD;                 // N*3
    float* out_csig     = out + (size_t)N_PTS * 19;                   // B
    float* out_cspatial = out + (size_t)N_PTS * 19 + NSEG;            // N
    float* out_action   = out + (size_t)N_PTS * 20 + NSEG;            // B*8
    float* out_hnext    = out + (size_t)N_PTS * 20 + NSEG + NSEG * AA;// B*64

    point_kernel<<<NCTA, TPB>>>(pos, batch, Wf1, bf1, Wf2, bf2, Wg1, bg1,
                                Wg2, bg2, agent_h, Wh, bh,
                                out_aff, out_recon, out_cspatial);
    agent_kernel<<<NSEG, 192>>>(agent_h, Wx, bx, Wlat, blat, Wact, bact,
                                out_csig, out_action, out_hnext);
}

// round 17
// speedup vs baseline: 1.0075x; 1.0075x over previous
#include <cuda_runtime.h>
#include <cuda_fp16.h>
#include <math.h>
#include <stdint.h>

#define N_PTS   1000000
#define NSEG    64
#define AFFD    16
#define AH      64
#define AL      32
#define AA      8

#define TPB     128
#define WARPS   4
#define TPW     4                                   // tiles per warp
#define TILES_PER_CTA (WARPS * TPW)                 // 16
#define NUM_WT  (N_PTS / 32)                        // 31250 warp-tiles (exact)
#define NCTA    ((NUM_WT + TILES_PER_CTA - 1) / TILES_PER_CTA)  // 1954

#define ACC_STRIDE 18   // 16 aff sums, err sum, count
#define FULL 0xffffffffu

// global scratch (no allocs allowed)
__device__ float g_accum[NSEG * ACC_STRIDE];
__device__ float g_gh[NSEG * 3 * AH];   // precomputed agent_h @ Wh + bh

// ---- fp16 helpers ----
__device__ __forceinline__ uint32_t pack_h2(float lo, float hi) {
    __half2 h = __floats2half2_rn(lo, hi);
    return *reinterpret_cast<uint32_t*>(&h);
}
// split (x,y) into fp16 hi pair and 64x-scaled fp16 residual pair
__device__ __forceinline__ void split_f16(float x, float y, uint32_t& hi, uint32_t& lo) {
    __half2 h = __floats2half2_rn(x, y);
    float2 b = __half22float2(h);
    __half2 l = __floats2half2_rn((x - b.x) * 64.0f, (y - b.y) * 64.0f);
    hi = *reinterpret_cast<uint32_t*>(&h);
    lo = *reinterpret_cast<uint32_t*>(&l);
}
__device__ __forceinline__ void mma_f16(float (&c)[4], const uint32_t (&a)[4], uint2 b) {
    asm volatile(
        "mma.sync.aligned.m16n8k16.row.col.f32.f16.f16.f32 "
        "{%0,%1,%2,%3}, {%4,%5,%6,%7}, {%8,%9}, {%0,%1,%2,%3};"
        : "+f"(c[0]), "+f"(c[1]), "+f"(c[2]), "+f"(c[3])
        : "r"(a[0]), "r"(a[1]), "r"(a[2]), "r"(a[3]), "r"(b.x), "r"(b.y));
}

// ---- tf32 helpers (layer1, K=4 real, k8 tile with hi|lo folded) ----
__device__ __forceinline__ uint32_t cvt_tf32(float f) {
    uint32_t r;
    asm("cvt.rna.tf32.f32 %0, %1;" : "=r"(r) : "f"(f));
    return r;
}
// A cols 0-3 = hi, cols 4-7 = lo; B rows 4-7 duplicate rows 0-3 (b1 == b0).
__device__ __forceinline__ void mma_tf32k8(float (&c)[4],
                                           uint32_t a0, uint32_t a1,
                                           uint32_t a2, uint32_t a3,
                                           uint32_t b0) {
    asm volatile(
        "mma.sync.aligned.m16n8k8.row.col.f32.tf32.tf32.f32 "
        "{%0,%1,%2,%3}, {%4,%5,%6,%7}, {%8,%8}, {%0,%1,%2,%3};"
        : "+f"(c[0]), "+f"(c[1]), "+f"(c[2]), "+f"(c[3])
        : "r"(a0), "r"(a1), "r"(a2), "r"(a3), "r"(b0));
}

__global__ __launch_bounds__(TPB, 5) void point_kernel(
    const float* __restrict__ pos, const int* __restrict__ batch,
    const float* __restrict__ Wf1, const float* __restrict__ bf1,
    const float* __restrict__ Wf2, const float* __restrict__ bf2,
    const float* __restrict__ Wg1, const float* __restrict__ bg1,
    const float* __restrict__ Wg2, const float* __restrict__ bg2,
    const float* __restrict__ agent_h, const float* __restrict__ Wh,
    const float* __restrict__ bh,
    float* __restrict__ out_aff, float* __restrict__ out_recon,
    float* __restrict__ out_cspatial)
{
    __shared__ uint32_t sB1[512];                        // [nt(16)][lane] tf32
    __shared__ uint2    sB2h[512], sB2s[512];            // [kt(8)][ni(2)][lane]
    __shared__ uint2    sB3h[512];                       // [nt(16)][lane] hi-only
    __shared__ uint2    sB4h[256];                       // [kt4(8)][lane] (Wg2, N=8 pad, hi-only)
    __shared__ float sbg1[128];
    __shared__ float sbf2[16];
    __shared__ float sacc[NSEG * ACC_STRIDE];
    __shared__ float s_h0[AH];

    const int tid = threadIdx.x;
    const int lane = tid & 31, wid = tid >> 5;
    const int gid = lane >> 2, tig = lane & 3;

    // ---- CTAs 0..63: precompute gh = agent_h @ Wh + bh (input-only; overlaps) ----
    if (blockIdx.x < NSEG) {
        int b = blockIdx.x;
        if (tid < AH) s_h0[tid] = agent_h[b * AH + tid];
        __syncthreads();
        for (int o = tid; o < 3 * AH; o += TPB) {
            float acc = bh[o];
            #pragma unroll 8
            for (int k = 0; k < AH; k++)
                acc = fmaf(s_h0[k], Wh[k * 3 * AH + o], acc);
            g_gh[b * 3 * AH + o] = acc;
        }
    }

    // ---- CTA init: pack B fragments from gmem weights (L1/L2 resident) ----
    for (int s = tid; s < 512; s += TPB) {
        int ls = s & 31, gs = ls >> 2, ts = ls & 3;
        {   // B1 (tf32): rows 0..2 = Wf1, 3 = bf1
            int nt = s >> 5;
            int n = nt * 8 + gs;
            float v = (ts == 0) ? Wf1[n] : (ts == 1) ? Wf1[128 + n]
                    : (ts == 2) ? Wf1[256 + n] : bf1[n];
            sB1[s] = cvt_tf32(v);
        }
        {   // B2: Wf2 [128k x 16n], slot s = (kt*2+ni)*32 + lane
            int ni = (s >> 5) & 1, kt = s >> 6;
            int n = ni * 8 + gs;
            int k0 = kt * 16 + 2 * ts;
            float w00 = Wf2[k0 * 16 + n],       w01 = Wf2[(k0 + 1) * 16 + n];
            float w10 = Wf2[(k0 + 8) * 16 + n], w11 = Wf2[(k0 + 9) * 16 + n];
            sB2h[s] = make_uint2(pack_h2(w00, w01), pack_h2(w10, w11));
            float q00 = __half2float(__float2half_rn(w00)) * 0.015625f;
            float q01 = __half2float(__float2half_rn(w01)) * 0.015625f;
            float q10 = __half2float(__float2half_rn(w10)) * 0.015625f;
            float q11 = __half2float(__float2half_rn(w11)) * 0.015625f;
            sB2s[s] = make_uint2(pack_h2(q00, q01), pack_h2(q10, q11));
        }
        {   // B3: Wg1 [16k x 128n], hi-only, slot s = nt*32 + lane
            int nt = s >> 5;
            int n = nt * 8 + gs;
            int k0 = 2 * ts;
            float v00 = Wg1[k0 * 128 + n],       v01 = Wg1[(k0 + 1) * 128 + n];
            float v10 = Wg1[(k0 + 8) * 128 + n], v11 = Wg1[(k0 + 9) * 128 + n];
            sB3h[s] = make_uint2(pack_h2(v00, v01), pack_h2(v10, v11));
        }
    }
    // B4: Wg2 [128k x 3n] padded to N=8, hi-only (recon tolerates fp16 rounding)
    for (int s = tid; s < 256; s += TPB) {
        int ls = s & 31, gs = ls >> 2, ts = ls & 3;
        int kt4 = s >> 5;
        int k0 = kt4 * 16 + 2 * ts;
        float v0 = (gs < 3) ? Wg2[k0 * 3 + gs] : 0.f;
        float v1 = (gs < 3) ? Wg2[(k0 + 1) * 3 + gs] : 0.f;
        float v2 = (gs < 3) ? Wg2[(k0 + 8) * 3 + gs] : 0.f;
        float v3 = (gs < 3) ? Wg2[(k0 + 9) * 3 + gs] : 0.f;
        sB4h[s] = make_uint2(pack_h2(v0, v1), pack_h2(v2, v3));
    }
    if (tid < 128) {
        sbg1[tid] = bg1[tid];
        if (tid < 16) sbf2[tid] = bf2[tid];
    }
    for (int i = tid; i < NSEG * ACC_STRIDE; i += TPB) sacc[i] = 0.f;
    __syncthreads();

    // ---- main: 4 warp-tiles per warp, sequential (init amortized) ----
    for (int t = 0; t < TPW; t++) {
        const int wt = blockIdx.x * TILES_PER_CTA + wid * TPW + t;
        if (wt >= NUM_WT) break;

        const int base = wt * 32;
        const int p = base + lane;
        const float px = pos[p * 3], py = pos[p * 3 + 1], pz = pos[p * 3 + 2];
        const int sg = batch[p];

        // ---- layer1 A fragments via direct LDG (row = base+gid+8j, col = tig) ----
        uint32_t A1hi[2][2], A1lo[2][2];
        #pragma unroll
        for (int j = 0; j < 4; j++) {
            int row = base + gid + 8 * j;
            int idx = min(row * 3 + tig, 3 * N_PTS - 1);
            float vm = pos[idx];
            float v = (tig == 3) ? 1.0f : vm;
            uint32_t hi = cvt_tf32(v);
            A1hi[j >> 1][j & 1] = hi;
            A1lo[j >> 1][j & 1] = cvt_tf32(v - __uint_as_float(hi));
        }

        // ---- layer2 accumulators (aff), init with bf2 bias ----
        float C2[2][2][4];
        #pragma unroll
        for (int ni = 0; ni < 2; ni++) {
            float be = sbf2[ni * 8 + 2 * tig];
            float bo = sbf2[ni * 8 + 2 * tig + 1];
            #pragma unroll
            for (int mi = 0; mi < 2; mi++) {
                C2[mi][ni][0] = be; C2[mi][ni][1] = bo;
                C2[mi][ni][2] = be; C2[mi][ni][3] = bo;
            }
        }

        // ---- fused layer1(tf32 k8) -> relu/split -> layer2(fp16 2-term) ----
        #pragma unroll 2
        for (int kt = 0; kt < 8; kt++) {
            float C1[2][2][4];
            uint32_t b_a = sB1[(2 * kt) * 32 + lane];
            uint32_t b_b = sB1[(2 * kt + 1) * 32 + lane];
            #pragma unroll
            for (int ntl = 0; ntl < 2; ntl++)
                #pragma unroll
                for (int mi = 0; mi < 2; mi++) {
                    float (&c)[4] = C1[ntl][mi];
                    c[0] = 0.f; c[1] = 0.f; c[2] = 0.f; c[3] = 0.f;
                    mma_tf32k8(c, A1hi[mi][0], A1hi[mi][1],
                                  A1lo[mi][0], A1lo[mi][1],
                                  ntl ? b_b : b_a);
                }

            uint32_t a2h[2][4], a2l[2][4];
            #pragma unroll
            for (int mi = 0; mi < 2; mi++) {
                float r00 = fmaxf(C1[0][mi][0], 0.f), r01 = fmaxf(C1[0][mi][1], 0.f);
                float r02 = fmaxf(C1[0][mi][2], 0.f), r03 = fmaxf(C1[0][mi][3], 0.f);
                float r10 = fmaxf(C1[1][mi][0], 0.f), r11 = fmaxf(C1[1][mi][1], 0.f);
                float r12 = fmaxf(C1[1][mi][2], 0.f), r13 = fmaxf(C1[1][mi][3], 0.f);
                split_f16(r00, r01, a2h[mi][0], a2l[mi][0]);
                split_f16(r02, r03, a2h[mi][1], a2l[mi][1]);
                split_f16(r10, r11, a2h[mi][2], a2l[mi][2]);
                split_f16(r12, r13, a2h[mi][3], a2l[mi][3]);
            }

            #pragma unroll
            for (int ni = 0; ni < 2; ni++) {
                uint2 bhv = sB2h[(kt * 2 + ni) * 32 + lane];
                uint2 bsv = sB2s[(kt * 2 + ni) * 32 + lane];
                #pragma unroll
                for (int mi = 0; mi < 2; mi++) {
                    mma_f16(C2[mi][ni], a2h[mi], bhv);
                    mma_f16(C2[mi][ni], a2l[mi], bsv);
                }
            }
        }

        // ---- store affordances: direct STG.64 ----
        #pragma unroll
        for (int mi = 0; mi < 2; mi++)
            #pragma unroll
            for (int ni = 0; ni < 2; ni++) {
                int r0 = base + 16 * mi + gid;
                int c0 = ni * 8 + 2 * tig;
                *(float2*)(out_aff + (size_t)r0 * 16 + c0) =
                    make_float2(C2[mi][ni][0], C2[mi][ni][1]);
                *(float2*)(out_aff + (size_t)(r0 + 8) * 16 + c0) =
                    make_float2(C2[mi][ni][2], C2[mi][ni][3]);
            }

        // ---- layer3 A fragments directly from C2 (hi-only) ----
        uint32_t a3h[2][4];
        #pragma unroll
        for (int mi = 0; mi < 2; mi++) {
            a3h[mi][0] = pack_h2(C2[mi][0][0], C2[mi][0][1]);
            a3h[mi][1] = pack_h2(C2[mi][0][2], C2[mi][0][3]);
            a3h[mi][2] = pack_h2(C2[mi][1][0], C2[mi][1][1]);
            a3h[mi][3] = pack_h2(C2[mi][1][2], C2[mi][1][3]);
        }

        // ---- layer3 (fp16 hi-only MMA) -> relu/pack -> layer4 (fp16 hi-only MMA) ----
        float C4[2][4];
        C4[0][0] = 0.f; C4[0][1] = 0.f; C4[0][2] = 0.f; C4[0][3] = 0.f;
        C4[1][0] = 0.f; C4[1][1] = 0.f; C4[1][2] = 0.f; C4[1][3] = 0.f;

        #pragma unroll 2
        for (int kt4 = 0; kt4 < 8; kt4++) {
            int nt0 = 2 * kt4, nt1 = 2 * kt4 + 1;
            uint2 bh0 = sB3h[nt0 * 32 + lane];
            uint2 bh1 = sB3h[nt1 * 32 + lane];
            float be0 = sbg1[nt0 * 8 + 2 * tig], bo0 = sbg1[nt0 * 8 + 2 * tig + 1];
            float be1 = sbg1[nt1 * 8 + 2 * tig], bo1 = sbg1[nt1 * 8 + 2 * tig + 1];
            uint2 b4h = sB4h[kt4 * 32 + lane];
            #pragma unroll
            for (int mi = 0; mi < 2; mi++) {
                float gE[4] = {be0, bo0, be0, bo0};
                mma_f16(gE, a3h[mi], bh0);
                float gO[4] = {be1, bo1, be1, bo1};
                mma_f16(gO, a3h[mi], bh1);
                uint32_t a4h[4];
                a4h[0] = pack_h2(fmaxf(gE[0], 0.f), fmaxf(gE[1], 0.f));
                a4h[1] = pack_h2(fmaxf(gE[2], 0.f), fmaxf(gE[3], 0.f));
                a4h[2] = pack_h2(fmaxf(gO[0], 0.f), fmaxf(gO[1], 0.f));
                a4h[3] = pack_h2(fmaxf(gO[2], 0.f), fmaxf(gO[3], 0.f));
                mma_f16(C4[mi], a4h, b4h);
            }
        }

        // ---- extract recon for this lane's own row (row = lane) ----
        const int src0 = (lane & 7) * 4;
        const int src1 = src0 + 1;
        const bool h8 = (lane & 8) != 0;
        const bool h16 = (lane & 16) != 0;
        float xa = __shfl_sync(FULL, C4[0][0], src0);
        float xb = __shfl_sync(FULL, C4[0][2], src0);
        float xc = __shfl_sync(FULL, C4[1][0], src0);
        float xd = __shfl_sync(FULL, C4[1][2], src0);
        float ya = __shfl_sync(FULL, C4[0][1], src0);
        float yb = __shfl_sync(FULL, C4[0][3], src0);
        float yc = __shfl_sync(FULL, C4[1][1], src0);
        float yd = __shfl_sync(FULL, C4[1][3], src0);
        float za = __shfl_sync(FULL, C4[0][0], src1);
        float zb = __shfl_sync(FULL, C4[0][2], src1);
        float zc = __shfl_sync(FULL, C4[1][0], src1);
        float zd = __shfl_sync(FULL, C4[1][2], src1);
        float rxx = (h16 ? (h8 ? xd : xc) : (h8 ? xb : xa)) + bg2[0];
        float ryy = (h16 ? (h8 ? yd : yc) : (h8 ? yb : ya)) + bg2[1];
        float rzz = (h16 ? (h8 ? zd : zc) : (h8 ? zb : za)) + bg2[2];

        float dx = px - rxx, dy = py - ryy, dz = pz - rzz;
        float e = fmaf(dx, dx, fmaf(dy, dy, dz * dz));
        out_recon[(size_t)p * 3 + 0] = rxx;
        out_recon[(size_t)p * 3 + 1] = ryy;
        out_recon[(size_t)p * 3 + 2] = rzz;
        out_cspatial[p] = e;

        // ---- segment reduction ----
        int sg0 = __shfl_sync(FULL, sg, 0);
        bool uni = __all_sync(FULL, sg == sg0);
        if (uni) {
            float s0 = C2[0][0][0] + C2[0][0][2] + C2[1][0][0] + C2[1][0][2];
            float s1 = C2[0][0][1] + C2[0][0][3] + C2[1][0][1] + C2[1][0][3];
            float s2 = C2[0][1][0] + C2[0][1][2] + C2[1][1][0] + C2[1][1][2];
            float s3 = C2[0][1][1] + C2[0][1][3] + C2[1][1][1] + C2[1][1][3];
            #pragma unroll
            for (int off = 4; off <= 16; off <<= 1) {
                s0 += __shfl_xor_sync(FULL, s0, off);
                s1 += __shfl_xor_sync(FULL, s1, off);
                s2 += __shfl_xor_sync(FULL, s2, off);
                s3 += __shfl_xor_sync(FULL, s3, off);
            }
            if (lane < 4) {
                float* a = sacc + sg0 * ACC_STRIDE;
                atomicAdd(a + 2 * tig, s0);
                atomicAdd(a + 2 * tig + 1, s1);
                atomicAdd(a + 2 * tig + 8, s2);
                atomicAdd(a + 2 * tig + 9, s3);
            }
            float es = e;
            #pragma unroll
            for (int off = 1; off <= 16; off <<= 1)
                es += __shfl_xor_sync(FULL, es, off);
            if (lane == 0) {
                atomicAdd(sacc + sg0 * ACC_STRIDE + 16, es);
                atomicAdd(sacc + sg0 * ACC_STRIDE + 17, 32.f);
            }
        } else {
            int bseg[4];
            #pragma unroll
            for (int j = 0; j < 4; j++) bseg[j] = batch[base + gid + 8 * j];
            #pragma unroll
            for (int mi = 0; mi < 2; mi++) {
                float* a0 = sacc + bseg[2 * mi] * ACC_STRIDE;
                float* a1 = sacc + bseg[2 * mi + 1] * ACC_STRIDE;
                #pragma unroll
                for (int ni = 0; ni < 2; ni++) {
                    atomicAdd(a0 + ni * 8 + 2 * tig,     C2[mi][ni][0]);
                    atomicAdd(a0 + ni * 8 + 2 * tig + 1, C2[mi][ni][1]);
                    atomicAdd(a1 + ni * 8 + 2 * tig,     C2[mi][ni][2]);
                    atomicAdd(a1 + ni * 8 + 2 * tig + 1, C2[mi][ni][3]);
                }
            }
            atomicAdd(sacc + sg * ACC_STRIDE + 16, e);
            atomicAdd(sacc + sg * ACC_STRIDE + 17, 1.f);
        }
    }
    __syncthreads();

    // ---- flush CTA's segment range (batch sorted; 512 points per CTA) ----
    int first = blockIdx.x * TILES_PER_CTA * 32;
    if (first < N_PTS) {
        int last = min(first + TILES_PER_CTA * 32 - 1, N_PTS - 1);
        int smin = batch[first];
        int smax = batch[last];
        int total = (smax - smin + 1) * ACC_STRIDE;
        for (int t = tid; t < total; t += TPB) {
            float v = sacc[smin * ACC_STRIDE + t];
            if (v != 0.f) atomicAdd(&g_accum[smin * ACC_STRIDE + t], v);
        }
    }
}

// fast transcendentals (2-ulp __expf): error ~1e-6, negligible vs 1e-3 budget
__device__ __forceinline__ float fast_sigmoid(float x) {
    return 1.0f / (1.0f + __expf(-x));
}
__device__ __forceinline__ float fast_tanh(float x) {
    return 2.0f / (1.0f + __expf(-2.0f * x)) - 1.0f;
}

// latency-optimized: L1 pre-warm for later phases, no SMEM staging of aff/h
__global__ __launch_bounds__(192) void agent_kernel(
    const float* __restrict__ agent_h,
    const float* __restrict__ Wx, const float* __restrict__ bx,
    const float* __restrict__ Wlat, const float* __restrict__ blat,
    const float* __restrict__ Wact, const float* __restrict__ bact,
    float* __restrict__ out_csig, float* __restrict__ out_action,
    float* __restrict__ out_hnext)
{
    int b = blockIdx.x;
    int u = threadIdx.x;   // 0..191
    __shared__ float sRZ[2 * AH];
    __shared__ float sGN[AH];
    __shared__ float sHN[AH];
    __shared__ float s_hn[AH];
    __shared__ float s_lat[AL];
    __shared__ float s_sink;

    // ---- L1 pre-warm for phase-3/4 weights (issued early; blocks only at use) ----
    float warm = 0.f;
    for (int i = u; i < AH * AL; i += 192) warm += Wlat[i];
    for (int i = u; i < AL * AA; i += 192) warm += Wact[i];

    // ---- phase 1: gates. aff read directly from g_accum (broadcast loads) ----
    float cnt = g_accum[b * ACC_STRIDE + 17];
    float invd = 1.0f / fmaxf(cnt, 1.0f);
    if (u == 0) out_csig[b] = g_accum[b * ACC_STRIDE + 16] * invd;

    float gx = bx[u];
    #pragma unroll
    for (int k = 0; k < AFFD; k++)
        gx = fmaf(g_accum[b * ACC_STRIDE + k] * invd, Wx[k * 192 + u], gx);
    float gh = g_gh[b * 192 + u];   // precomputed in point_kernel

    if (u < 2 * AH) sRZ[u] = gx + gh;
    else { sGN[u - 2 * AH] = gx; sHN[u - 2 * AH] = gh; }
    // consume warm value (never true; prevents DCE of the pre-warm loads)
    if (warm == 1e38f) s_sink = warm;
    __syncthreads();

    // re-zero accumulator for next graph replay (after all reads)
    if (u < ACC_STRIDE) g_accum[b * ACC_STRIDE + u] = 0.0f;

    // ---- phase 2: GRU elementwise ----
    if (u < AH) {
        float r = fast_sigmoid(sRZ[u]);
        float z = fast_sigmoid(sRZ[AH + u]);
        float n = fast_tanh(sGN[u] + r * sHN[u]);
        float hn = (1.0f - z) * n + z * agent_h[b * AH + u];
        out_hnext[b * AH + u] = hn;
        s_hn[u] = hn;
    }
    __syncthreads();

    // ---- phase 3: latent (Wlat now L1-hot) ----
    if (u < AL) {
        float acc = blat[u];
        #pragma unroll 8
        for (int k = 0; k < AH; k++) acc = fmaf(s_hn[k], Wlat[k * AL + u], acc);
        s_lat[u] = fast_tanh(acc);
    }
    __syncthreads();

    // ---- phase 4: action (Wact now L1-hot) ----
    if (u < AA) {
        float acc = bact[u];
        #pragma unroll
        for (int k = 0; k < AL; k++) acc = fmaf(s_lat[k], Wact[k * AA + u], acc);
        out_action[b * AA + u] = acc;
    }
}

extern "C" void kernel_launch(void* const* d_in, const int* in_sizes, int n_in,
                              void* d_out, int out_size) {
    const float* pos   = (const float*)d_in[0];
    const int*   batch = (const int*)d_in[1];
    const float* agent_h = (const float*)d_in[2];
    const float* Wf1 = (const float*)d_in[5];
    const float* bf1 = (const float*)d_in[6];
    const float* Wf2 = (const float*)d_in[7];
    const float* bf2 = (const float*)d_in[8];
    const float* Wg1 = (const float*)d_in[9];
    const float* bg1 = (const float*)d_in[10];
    const float* Wg2 = (const float*)d_in[11];
    const float* bg2 = (const float*)d_in[12];
    const float* Wx  = (const float*)d_in[13];
    const float* Wh  = (const float*)d_in[14];
    const float* bx  = (const float*)d_in[15];
    const float* bh  = (const float*)d_in[16];
    const float* Wlat = (const float*)d_in[17];
    const float* blat = (const float*)d_in[18];
    const float* Wact = (const float*)d_in[19];
    const float* bact = (const float*)d_in[20];

    float* out = (float*)d_out;
    float* out_aff      = out;                                        // N*16
    float* out_recon    = out + (size_t)N_PTS * AFFD;                 // N*3
    float* out_csig     = out + (size_t)N_PTS * 19;                   // B
    float* out_cspatial = out + (size_t)N_PTS * 19 + NSEG;            // N
    float* out_action   = out + (size_t)N_PTS * 20 + NSEG;            // B*8
    float* out_hnext    = out + (size_t)N_PTS * 20 + NSEG + NSEG * AA;// B*64

    point_kernel<<<NCTA, TPB>>>(pos, batch, Wf1, bf1, Wf2, bf2, Wg1, bg1,
                                Wg2, bg2, agent_h, Wh, bh,
                                out_aff, out_recon, out_cspatial);
    agent_kernel<<<NSEG, 192>>>(agent_h, Wx, bx, Wlat, blat, Wact, bact,
                                out_csig, out_action, out_hnext);
}